// round 5
// baseline (speedup 1.0000x reference)
#include <cuda_runtime.h>
#include <cuda_bf16.h>
#include <cstdint>

// ======================= problem constants =======================
#define DIMX     64
#define HIDX     256
#define NSTEPS   32
#define MTILE    256          // rows per CTA (16 warps x 16 rows)
#define NTHREADS 512

// ======================= SMEM layout (bytes) =====================
#define SM_B1   0
#define SM_TW1  1024
#define SM_B2   2048
#define SM_DB3  3072          // dt * b3 (fp32, 64)
#define SM_W1   4096          // 256n x 64k bf16, 128B rows, SW128    (32768 B)
#define SM_W2   36864         // 4 k-chunks x (256n x 64k)            (131072 B)
#define SM_W3   167936        // 4 k-chunks x (64n x 64k)             (32768 B)
#define SMEM_BYTES 200704

#define SWZ(off) ((off) ^ (((off) >> 3) & 0x70))

// ======================= device helpers ==========================
__device__ __forceinline__ uint32_t smem_to_u32(const void* p) {
    uint32_t a;
    asm("{ .reg .u64 t; cvta.to.shared.u64 t, %1; cvt.u32.u64 %0, t; }" : "=r"(a) : "l"(p));
    return a;
}
__device__ __forceinline__ uint32_t pack_bf16x2(float lo, float hi) {
    uint32_t r;
    asm("cvt.rn.bf16x2.f32 %0, %1, %2;" : "=r"(r) : "f"(hi), "f"(lo));
    return r;
}
__device__ __forceinline__ float fast_tanh(float x) {
    float y;
    asm("tanh.approx.f32 %0, %1;" : "=f"(y) : "f"(x));
    return y;
}
__device__ __forceinline__ float silu(float a) {
    return a * (0.5f * fast_tanh(0.5f * a) + 0.5f);   // 1 MUFU op
}
__device__ __forceinline__ void ldsm4(uint32_t& r0, uint32_t& r1, uint32_t& r2, uint32_t& r3,
                                      uint32_t addr) {
    asm volatile("ldmatrix.sync.aligned.m8n8.x4.shared.b16 {%0,%1,%2,%3}, [%4];"
                 : "=r"(r0), "=r"(r1), "=r"(r2), "=r"(r3) : "r"(addr));
}
__device__ __forceinline__ void mma_bf16(float* c, const uint32_t* a, uint32_t b0, uint32_t b1) {
    asm volatile("mma.sync.aligned.m16n8k16.row.col.f32.bf16.bf16.f32 "
                 "{%0,%1,%2,%3}, {%4,%5,%6,%7}, {%8,%9}, {%0,%1,%2,%3};"
                 : "+f"(c[0]), "+f"(c[1]), "+f"(c[2]), "+f"(c[3])
                 : "r"(a[0]), "r"(a[1]), "r"(a[2]), "r"(a[3]), "r"(b0), "r"(b1));
}

// ======================= kernel ==================================
__global__ void __launch_bounds__(NTHREADS, 1) flow_kernel(
    const float* __restrict__ x0, const float* __restrict__ W1,
    const float* __restrict__ b1, const float* __restrict__ W2,
    const float* __restrict__ b2, const float* __restrict__ W3,
    const float* __restrict__ b3, float* __restrict__ out)
{
    extern __shared__ char smem[];
    const uint32_t sbase = smem_to_u32(smem);
    const int tid  = threadIdx.x;
    const int wid  = tid >> 5;
    const int lane = tid & 31;

    float* sb1  = (float*)(smem + SM_B1);
    float* stw1 = (float*)(smem + SM_TW1);
    float* sb2  = (float*)(smem + SM_B2);
    float* sdb3 = (float*)(smem + SM_DB3);

    const float dt = 1.0f / NSTEPS;

    // ---------------- prologue: biases ----------------
    for (int i = tid; i < HIDX; i += NTHREADS) {
        sb1[i]  = b1[i];
        stw1[i] = W1[DIMX * HIDX + i];   // t-row of W1
        sb2[i]  = b2[i];
    }
    if (tid < DIMX) sdb3[tid] = dt * b3[tid];

    // ---------------- prologue: weights -> bf16, W^T layout (n rows, k contig), SW128 ----
    for (int idx = tid; idx < DIMX * HIDX; idx += NTHREADS) {          // W1 (64k,256n)
        int k = idx >> 8, n = idx & 255;
        uint32_t off = (uint32_t)(n * 128 + k * 2);
        *(__nv_bfloat16*)(smem + SM_W1 + SWZ(off)) = __float2bfloat16(W1[idx]);
    }
    for (int idx = tid; idx < HIDX * HIDX; idx += NTHREADS) {          // W2 (256k,256n)
        int k = idx >> 8, n = idx & 255;
        int c = k >> 6, kk = k & 63;
        uint32_t off = (uint32_t)(n * 128 + kk * 2);
        *(__nv_bfloat16*)(smem + SM_W2 + c * 32768 + SWZ(off)) = __float2bfloat16(W2[idx]);
    }
    for (int idx = tid; idx < HIDX * DIMX; idx += NTHREADS) {          // W3 (256k,64n)
        int k = idx >> 6, n = idx & 63;
        int c = k >> 6, kk = k & 63;
        uint32_t off = (uint32_t)(n * 128 + kk * 2);
        *(__nv_bfloat16*)(smem + SM_W3 + c * 8192 + SWZ(off)) = __float2bfloat16(W3[idx]);
    }
    __syncthreads();

    // ---------------- per-lane ldmatrix addressing ----------------
    const int r = lane & 7, g = lane >> 3;
    const uint32_t ld_row = (uint32_t)((r + ((g >> 1) << 3)) * 128);
    const uint32_t g1 = (uint32_t)(g & 1);
    #define KOFF(kt) ((((uint32_t)(((kt) << 1) | g1) ^ (uint32_t)r) << 4))

    // anti-phase stagger of GEMM2/3 chunk order for the 4 warps sharing an SMSP
    const int stag = (wid >> 2) * 2;   // 0,2,4,6

    // ---------------- load x: m16 per warp, fp32 C-fragment layout ----------------
    // x[nt*4 + {0,1}] = row rowA cols nt*8+q2,+1 ; x[nt*4 + {2,3}] = row rowB
    const long rowA = (long)blockIdx.x * MTILE + wid * 16 + (lane >> 2);
    const long rowB = rowA + 8;
    const int  q2 = (lane & 3) * 2;

    float x[32];
    #pragma unroll
    for (int nt = 0; nt < 8; nt++) {
        float2 a = *(const float2*)(x0 + rowA * DIMX + nt * 8 + q2);
        float2 b = *(const float2*)(x0 + rowB * DIMX + nt * 8 + q2);
        x[nt * 4 + 0] = a.x; x[nt * 4 + 1] = a.y;
        x[nt * 4 + 2] = b.x; x[nt * 4 + 3] = b.y;
    }

    uint32_t hA[64];   // GEMM2 A fragments: [kt*4 + j], kt=0..15 (16 cols each)

    #pragma unroll 1
    for (int s = 0; s < NSTEPS; s++) {
        const float tval = ((float)s + 0.5f) * dt;

        // ======== GEMM1: h = silu(x@W1 + b1 + t*tw1)  (M=16/warp, N=256, K=64) ======
        // A fragments packed from x on the fly (saves 16 persistent regs).
        #pragma unroll 1
        for (int pair = 0; pair < 16; pair++) {
            float C[8];
            #pragma unroll
            for (int i = 0; i < 8; i++) C[i] = 0.0f;
            const uint32_t base = sbase + SM_W1 + (uint32_t)(pair * 2048) + ld_row;
            #pragma unroll
            for (int kt = 0; kt < 4; kt++) {
                uint32_t w0, w1_, w2_, w3_;
                ldsm4(w0, w1_, w2_, w3_, base + KOFF(kt));
                uint32_t a[4];
                const float* xs = x + 2 * kt * 4;   // n-tiles 2kt, 2kt+1
                a[0] = pack_bf16x2(xs[0], xs[1]);
                a[1] = pack_bf16x2(xs[2], xs[3]);
                a[2] = pack_bf16x2(xs[4], xs[5]);
                a[3] = pack_bf16x2(xs[6], xs[7]);
                mma_bf16(C + 0, a, w0,  w1_);
                mma_bf16(C + 4, a, w2_, w3_);
            }
            const int col0 = pair * 16 + q2;
            float2 bA = *(const float2*)(sb1 + col0);
            float2 tA = *(const float2*)(stw1 + col0);
            float2 bB = *(const float2*)(sb1 + col0 + 8);
            float2 tB = *(const float2*)(stw1 + col0 + 8);
            const float bAx = fmaf(tval, tA.x, bA.x), bAy = fmaf(tval, tA.y, bA.y);
            const float bBx = fmaf(tval, tB.x, bB.x), bBy = fmaf(tval, tB.y, bB.y);
            uint32_t* h = hA + pair * 4;
            h[0] = pack_bf16x2(silu(C[0] + bAx), silu(C[1] + bAy));
            h[1] = pack_bf16x2(silu(C[2] + bAx), silu(C[3] + bAy));
            h[2] = pack_bf16x2(silu(C[4] + bBx), silu(C[5] + bBy));
            h[3] = pack_bf16x2(silu(C[6] + bBx), silu(C[7] + bBy));
        }

        // ==== GEMM2 (N=256,K=256) fused with GEMM3 (N=64,K=256), chunk = 32 cols ====
        // Chunk order rotated per warp-quad (anti-phase on each SMSP).
        // GEMM3 A pre-scaled by dt (exact, 2^-5); mma accumulates into fp32 x.
        #pragma unroll 1
        for (int chi = 0; chi < 8; chi++) {
            const int ch = (chi + stag) & 7;
            float C2[16];
            #pragma unroll
            for (int i = 0; i < 16; i++) C2[i] = 0.0f;

            const uint32_t w2base = sbase + SM_W2 + (uint32_t)(ch * 4096) + ld_row;
            #pragma unroll
            for (int kt = 0; kt < 16; kt++) {
                const uint32_t koff = (uint32_t)((kt >> 2) * 32768) + KOFF(kt & 3);
                const uint32_t* a = hA + kt * 4;
                uint32_t w0, w1_, w2_, w3_;
                ldsm4(w0, w1_, w2_, w3_, w2base + koff);
                mma_bf16(C2 + 0, a, w0,  w1_);
                mma_bf16(C2 + 4, a, w2_, w3_);
                ldsm4(w0, w1_, w2_, w3_, w2base + 2048u + koff);
                mma_bf16(C2 + 8,  a, w0,  w1_);
                mma_bf16(C2 + 12, a, w2_, w3_);
            }

            // ---- epilogue: gA = bf16(dt * silu(C2 + b2)) ----
            uint32_t gA[8];
            #pragma unroll
            for (int p = 0; p < 2; p++) {
                const int col0 = ch * 32 + p * 16 + q2;
                float2 bA = *(const float2*)(sb2 + col0);
                float2 bB = *(const float2*)(sb2 + col0 + 8);
                const float* c = C2 + p * 8;
                uint32_t* ga = gA + p * 4;
                ga[0] = pack_bf16x2(dt * silu(c[0] + bA.x), dt * silu(c[1] + bA.y));
                ga[1] = pack_bf16x2(dt * silu(c[2] + bA.x), dt * silu(c[3] + bA.y));
                ga[2] = pack_bf16x2(dt * silu(c[4] + bB.x), dt * silu(c[5] + bB.y));
                ga[3] = pack_bf16x2(dt * silu(c[6] + bB.x), dt * silu(c[7] + bB.y));
            }

            // ---- GEMM3 k-slices: x += gA @ W3[k = ch*32 .. +31] ----
            #pragma unroll
            for (int p = 0; p < 2; p++) {
                const int kt3 = ch * 2 + p;
                const uint32_t w3base = sbase + SM_W3 + (uint32_t)((kt3 >> 2) * 8192) + ld_row;
                const uint32_t k3off = KOFF(kt3 & 3);
                #pragma unroll
                for (int ntp = 0; ntp < 4; ntp++) {
                    uint32_t w0, w1_, w2_, w3_;
                    ldsm4(w0, w1_, w2_, w3_, w3base + (uint32_t)(ntp * 2048) + k3off);
                    mma_bf16(x + (2 * ntp) * 4,     gA + p * 4, w0,  w1_);
                    mma_bf16(x + (2 * ntp + 1) * 4, gA + p * 4, w2_, w3_);
                }
            }
        }

        // ---- x += dt * b3 (linear contribution) ----
        #pragma unroll
        for (int nt = 0; nt < 8; nt++) {
            float2 p = *(const float2*)(sdb3 + nt * 8 + q2);
            float* xs = x + nt * 4;
            xs[0] += p.x; xs[1] += p.y; xs[2] += p.x; xs[3] += p.y;
        }
    }

    // ---------------- store result ----------------
    #pragma unroll
    for (int nt = 0; nt < 8; nt++) {
        const float* xs = x + nt * 4;
        *(float2*)(out + rowA * DIMX + nt * 8 + q2) = make_float2(xs[0], xs[1]);
        *(float2*)(out + rowB * DIMX + nt * 8 + q2) = make_float2(xs[2], xs[3]);
    }
}

// ======================= launch ==================================
extern "C" void kernel_launch(void* const* d_in, const int* in_sizes, int n_in,
                              void* d_out, int out_size) {
    const float* x0 = (const float*)d_in[0];
    const float* W1 = (const float*)d_in[1];
    const float* b1 = (const float*)d_in[2];
    const float* W2 = (const float*)d_in[3];
    const float* b2 = (const float*)d_in[4];
    const float* W3 = (const float*)d_in[5];
    const float* b3 = (const float*)d_in[6];
    float* out = (float*)d_out;

    const int nrows = in_sizes[0] / DIMX;
    const int grid  = nrows / MTILE;   // 512

    cudaFuncSetAttribute(flow_kernel, cudaFuncAttributeMaxDynamicSharedMemorySize, SMEM_BYTES);
    flow_kernel<<<grid, NTHREADS, SMEM_BYTES>>>(x0, W1, b1, W2, b2, W3, b3, out);
}

// round 6
// speedup vs baseline: 1.1770x; 1.1770x over previous
#include <cuda_runtime.h>
#include <cuda_bf16.h>
#include <cstdint>

// ======================= problem constants =======================
#define DIMX     64
#define HIDX     256
#define NSTEPS   32
#define MTILE    256          // rows per CTA (8 warps x 32 rows)
#define NTHREADS 256

// ======================= SMEM layout (bytes) =====================
#define SM_B1   0
#define SM_TW1  1024
#define SM_B2   2048
#define SM_DB3  3072          // dt * b3 (fp32, 64)
#define SM_W1   4096          // 256n x 64k bf16, 128B rows, SW128    (32768 B)
#define SM_W2   36864         // 4 k-chunks x (256n x 64k)            (131072 B)
#define SM_W3   167936        // 4 k-chunks x (64n x 64k)             (32768 B)
#define SMEM_BYTES 200704

#define SWZ(off) ((off) ^ (((off) >> 3) & 0x70))

// ======================= device helpers ==========================
__device__ __forceinline__ uint32_t smem_to_u32(const void* p) {
    uint32_t a;
    asm("{ .reg .u64 t; cvta.to.shared.u64 t, %1; cvt.u32.u64 %0, t; }" : "=r"(a) : "l"(p));
    return a;
}
__device__ __forceinline__ uint32_t pack_bf16x2(float lo, float hi) {
    uint32_t r;
    asm("cvt.rn.bf16x2.f32 %0, %1, %2;" : "=r"(r) : "f"(hi), "f"(lo));
    return r;
}
__device__ __forceinline__ float fast_tanh(float x) {
    float y;
    asm("tanh.approx.f32 %0, %1;" : "=f"(y) : "f"(x));
    return y;
}
__device__ __forceinline__ float silu(float a) {
    return a * (0.5f * fast_tanh(0.5f * a) + 0.5f);   // 1 MUFU op
}
__device__ __forceinline__ void ldsm4(uint32_t& r0, uint32_t& r1, uint32_t& r2, uint32_t& r3,
                                      uint32_t addr) {
    asm volatile("ldmatrix.sync.aligned.m8n8.x4.shared.b16 {%0,%1,%2,%3}, [%4];"
                 : "=r"(r0), "=r"(r1), "=r"(r2), "=r"(r3) : "r"(addr));
}
__device__ __forceinline__ void mma_bf16(float* c, const uint32_t* a, uint32_t b0, uint32_t b1) {
    asm volatile("mma.sync.aligned.m16n8k16.row.col.f32.bf16.bf16.f32 "
                 "{%0,%1,%2,%3}, {%4,%5,%6,%7}, {%8,%9}, {%0,%1,%2,%3};"
                 : "+f"(c[0]), "+f"(c[1]), "+f"(c[2]), "+f"(c[3])
                 : "r"(a[0]), "r"(a[1]), "r"(a[2]), "r"(a[3]), "r"(b0), "r"(b1));
}

// ======================= kernel ==================================
__global__ void __launch_bounds__(NTHREADS, 1) flow_kernel(
    const float* __restrict__ x0, const float* __restrict__ W1,
    const float* __restrict__ b1, const float* __restrict__ W2,
    const float* __restrict__ b2, const float* __restrict__ W3,
    const float* __restrict__ b3, float* __restrict__ out)
{
    extern __shared__ char smem[];
    const uint32_t sbase = smem_to_u32(smem);
    const int tid  = threadIdx.x;
    const int wid  = tid >> 5;
    const int lane = tid & 31;

    float* sb1  = (float*)(smem + SM_B1);
    float* stw1 = (float*)(smem + SM_TW1);
    float* sb2  = (float*)(smem + SM_B2);
    float* sdb3 = (float*)(smem + SM_DB3);

    const float dt = 1.0f / NSTEPS;

    // ---------------- prologue: biases ----------------
    for (int i = tid; i < HIDX; i += NTHREADS) {
        sb1[i]  = b1[i];
        stw1[i] = W1[DIMX * HIDX + i];   // t-row of W1
        sb2[i]  = b2[i];
    }
    if (tid < DIMX) sdb3[tid] = dt * b3[tid];

    // ---------------- prologue: weights -> bf16, W^T layout (n rows, k contig), SW128 ----
    for (int idx = tid; idx < DIMX * HIDX; idx += NTHREADS) {          // W1 (64k,256n)
        int k = idx >> 8, n = idx & 255;
        uint32_t off = (uint32_t)(n * 128 + k * 2);
        *(__nv_bfloat16*)(smem + SM_W1 + SWZ(off)) = __float2bfloat16(W1[idx]);
    }
    for (int idx = tid; idx < HIDX * HIDX; idx += NTHREADS) {          // W2 (256k,256n)
        int k = idx >> 8, n = idx & 255;
        int c = k >> 6, kk = k & 63;
        uint32_t off = (uint32_t)(n * 128 + kk * 2);
        *(__nv_bfloat16*)(smem + SM_W2 + c * 32768 + SWZ(off)) = __float2bfloat16(W2[idx]);
    }
    for (int idx = tid; idx < HIDX * DIMX; idx += NTHREADS) {          // W3 (256k,64n)
        int k = idx >> 6, n = idx & 63;
        int c = k >> 6, kk = k & 63;
        uint32_t off = (uint32_t)(n * 128 + kk * 2);
        *(__nv_bfloat16*)(smem + SM_W3 + c * 8192 + SWZ(off)) = __float2bfloat16(W3[idx]);
    }
    __syncthreads();

    // ---------------- per-lane ldmatrix addressing ----------------
    const int r = lane & 7, g = lane >> 3;
    const uint32_t ld_row = (uint32_t)((r + ((g >> 1) << 3)) * 128);
    const uint32_t g1 = (uint32_t)(g & 1);
    #define KOFF(kt) ((((uint32_t)(((kt) << 1) | g1) ^ (uint32_t)r) << 4))

    // anti-phase stagger: SMSP partner warps (wid, wid+4) offset by half the loop
    const int stag8 = (wid >> 2) * 8;   // 0 or 8

    // ---------------- load x: m32 per warp, fp32 C-fragment layout ----------------
    const long rowBase = (long)blockIdx.x * MTILE + wid * 32 + (lane >> 2);
    const int  q2 = (lane & 3) * 2;

    float x[64];
    #pragma unroll
    for (int mt = 0; mt < 2; mt++) {
        const float* pA = x0 + (rowBase + mt * 16) * DIMX;
        const float* pB = x0 + (rowBase + mt * 16 + 8) * DIMX;
        #pragma unroll
        for (int nt = 0; nt < 8; nt++) {
            float2 a = *(const float2*)(pA + nt * 8 + q2);
            float2 b = *(const float2*)(pB + nt * 8 + q2);
            x[(mt * 8 + nt) * 4 + 0] = a.x; x[(mt * 8 + nt) * 4 + 1] = a.y;
            x[(mt * 8 + nt) * 4 + 2] = b.x; x[(mt * 8 + nt) * 4 + 3] = b.y;
        }
    }

    uint32_t hA[128];   // GEMM2 A fragments: [(kt*2+mt)*4 + j], kt=0..15

    #pragma unroll 1
    for (int s = 0; s < NSTEPS; s++) {
        const float tval = ((float)s + 0.5f) * dt;

        // ---- x -> bf16 A fragments for GEMM1: xA[(kt*2+mt)*4+j], kt=0..3 ----
        uint32_t xA[32];
        #pragma unroll
        for (int kt = 0; kt < 4; kt++) {
            #pragma unroll
            for (int mt = 0; mt < 2; mt++) {
                const float* xs = x + (mt * 8 + 2 * kt) * 4;
                uint32_t* a = xA + (kt * 2 + mt) * 4;
                a[0] = pack_bf16x2(xs[0], xs[1]);
                a[1] = pack_bf16x2(xs[2], xs[3]);
                a[2] = pack_bf16x2(xs[4], xs[5]);
                a[3] = pack_bf16x2(xs[6], xs[7]);
            }
        }

        // ======== GEMM1: h = silu(x@W1 + b1 + t*tw1)  (M=32/warp, N=256, K=64) ======
        #pragma unroll 1
        for (int pi = 0; pi < 16; pi++) {
            const int pair = (pi + stag8) & 15;
            float C[16];
            #pragma unroll
            for (int i = 0; i < 16; i++) C[i] = 0.0f;
            const uint32_t base = sbase + SM_W1 + (uint32_t)(pair * 2048) + ld_row;
            #pragma unroll
            for (int kt = 0; kt < 4; kt++) {
                uint32_t w0, w1_, w2_, w3_;
                ldsm4(w0, w1_, w2_, w3_, base + KOFF(kt));
                mma_bf16(C + 0,  xA + (kt * 2 + 0) * 4, w0,  w1_);
                mma_bf16(C + 4,  xA + (kt * 2 + 0) * 4, w2_, w3_);
                mma_bf16(C + 8,  xA + (kt * 2 + 1) * 4, w0,  w1_);
                mma_bf16(C + 12, xA + (kt * 2 + 1) * 4, w2_, w3_);
            }
            const int col0 = pair * 16 + q2;
            float2 bA = *(const float2*)(sb1 + col0);
            float2 tA = *(const float2*)(stw1 + col0);
            float2 bB = *(const float2*)(sb1 + col0 + 8);
            float2 tB = *(const float2*)(stw1 + col0 + 8);
            const float bAx = fmaf(tval, tA.x, bA.x), bAy = fmaf(tval, tA.y, bA.y);
            const float bBx = fmaf(tval, tB.x, bB.x), bBy = fmaf(tval, tB.y, bB.y);
            #pragma unroll
            for (int mt = 0; mt < 2; mt++) {
                const float* c = C + mt * 8;
                uint32_t* h = hA + (pair * 2 + mt) * 4;
                h[0] = pack_bf16x2(silu(c[0] + bAx), silu(c[1] + bAy));
                h[1] = pack_bf16x2(silu(c[2] + bAx), silu(c[3] + bAy));
                h[2] = pack_bf16x2(silu(c[4] + bBx), silu(c[5] + bBy));
                h[3] = pack_bf16x2(silu(c[6] + bBx), silu(c[7] + bBy));
            }
        }

        // ==== GEMM2 (N=256,K=256) fused with GEMM3 (N=64,K=256), chunk = 16 cols ====
        // B fragments double-buffered (ldsm for kt+1 overlaps kt's mma chain).
        // GEMM3 A pre-scaled by dt (exact, 2^-5); mma accumulates into fp32 x.
        #pragma unroll 1
        for (int chi = 0; chi < 16; chi++) {
            const int ch = (chi + stag8) & 15;
            float C2[16];
            #pragma unroll
            for (int i = 0; i < 16; i++) C2[i] = 0.0f;

            const uint32_t w2base = sbase + SM_W2 + (uint32_t)(ch * 2048) + ld_row;
            uint32_t cw0, cw1, cw2, cw3;
            ldsm4(cw0, cw1, cw2, cw3, w2base + KOFF(0));
            #pragma unroll
            for (int kt = 0; kt < 16; kt++) {
                uint32_t nw0, nw1, nw2, nw3;
                if (kt < 15) {
                    const int kn = kt + 1;
                    ldsm4(nw0, nw1, nw2, nw3,
                          w2base + (uint32_t)((kn >> 2) * 32768) + KOFF(kn & 3));
                }
                mma_bf16(C2 + 0,  hA + (kt * 2 + 0) * 4, cw0, cw1);
                mma_bf16(C2 + 4,  hA + (kt * 2 + 0) * 4, cw2, cw3);
                mma_bf16(C2 + 8,  hA + (kt * 2 + 1) * 4, cw0, cw1);
                mma_bf16(C2 + 12, hA + (kt * 2 + 1) * 4, cw2, cw3);
                if (kt < 15) { cw0 = nw0; cw1 = nw1; cw2 = nw2; cw3 = nw3; }
            }

            // ---- epilogue: gA = bf16(dt * silu(C2 + b2)) ----
            const int col0 = ch * 16 + q2;
            float2 bA = *(const float2*)(sb2 + col0);
            float2 bB = *(const float2*)(sb2 + col0 + 8);
            uint32_t gA[8];
            #pragma unroll
            for (int mt = 0; mt < 2; mt++) {
                const float* c = C2 + mt * 8;
                uint32_t* ga = gA + mt * 4;
                ga[0] = pack_bf16x2(dt * silu(c[0] + bA.x), dt * silu(c[1] + bA.y));
                ga[1] = pack_bf16x2(dt * silu(c[2] + bA.x), dt * silu(c[3] + bA.y));
                ga[2] = pack_bf16x2(dt * silu(c[4] + bB.x), dt * silu(c[5] + bB.y));
                ga[3] = pack_bf16x2(dt * silu(c[6] + bB.x), dt * silu(c[7] + bB.y));
            }

            // ---- GEMM3 k-slice: x += gA @ W3[k = ch*16 .. +15] ----
            const uint32_t w3base = sbase + SM_W3 + (uint32_t)((ch >> 2) * 8192) + ld_row;
            const uint32_t k3off = KOFF(ch & 3);
            #pragma unroll
            for (int ntp = 0; ntp < 4; ntp++) {
                uint32_t w0, w1_, w2_, w3_;
                ldsm4(w0, w1_, w2_, w3_, w3base + (uint32_t)(ntp * 2048) + k3off);
                mma_bf16(x + (0 * 8 + 2 * ntp) * 4,     gA + 0, w0,  w1_);
                mma_bf16(x + (0 * 8 + 2 * ntp + 1) * 4, gA + 0, w2_, w3_);
                mma_bf16(x + (1 * 8 + 2 * ntp) * 4,     gA + 4, w0,  w1_);
                mma_bf16(x + (1 * 8 + 2 * ntp + 1) * 4, gA + 4, w2_, w3_);
            }
        }

        // ---- x += dt * b3 (linear contribution) ----
        #pragma unroll
        for (int nt = 0; nt < 8; nt++) {
            float2 p = *(const float2*)(sdb3 + nt * 8 + q2);
            #pragma unroll
            for (int mt = 0; mt < 2; mt++) {
                float* xs = x + (mt * 8 + nt) * 4;
                xs[0] += p.x; xs[1] += p.y; xs[2] += p.x; xs[3] += p.y;
            }
        }
    }

    // ---------------- store result ----------------
    #pragma unroll
    for (int mt = 0; mt < 2; mt++) {
        float* pA = out + (rowBase + mt * 16) * DIMX;
        float* pB = out + (rowBase + mt * 16 + 8) * DIMX;
        #pragma unroll
        for (int nt = 0; nt < 8; nt++) {
            const float* xs = x + (mt * 8 + nt) * 4;
            *(float2*)(pA + nt * 8 + q2) = make_float2(xs[0], xs[1]);
            *(float2*)(pB + nt * 8 + q2) = make_float2(xs[2], xs[3]);
        }
    }
}

// ======================= launch ==================================
extern "C" void kernel_launch(void* const* d_in, const int* in_sizes, int n_in,
                              void* d_out, int out_size) {
    const float* x0 = (const float*)d_in[0];
    const float* W1 = (const float*)d_in[1];
    const float* b1 = (const float*)d_in[2];
    const float* W2 = (const float*)d_in[3];
    const float* b2 = (const float*)d_in[4];
    const float* W3 = (const float*)d_in[5];
    const float* b3 = (const float*)d_in[6];
    float* out = (float*)d_out;

    const int nrows = in_sizes[0] / DIMX;
    const int grid  = nrows / MTILE;   // 512

    cudaFuncSetAttribute(flow_kernel, cudaFuncAttributeMaxDynamicSharedMemorySize, SMEM_BYTES);
    flow_kernel<<<grid, NTHREADS, SMEM_BYTES>>>(x0, W1, b1, W2, b2, W3, b3, out);
}

// round 7
// speedup vs baseline: 1.2208x; 1.0372x over previous
#include <cuda_runtime.h>
#include <cuda_bf16.h>
#include <cstdint>

// ======================= problem constants =======================
#define DIMX     64
#define HIDX     256
#define NSTEPS   32
#define MTILE    128          // rows per CTA (8 warps x 16 rows)
#define NTHREADS 256

// ======================= SMEM layout (bytes) =====================
#define SM_B1   0
#define SM_TW1  1024
#define SM_B2   2048
#define SM_DB3  3072          // dt * b3 (fp32, 64)
#define SM_W1   4096          // 256n x 64k bf16, 128B rows, SW128    (32768 B)
#define SM_W2   36864         // 4 k-chunks x (256n x 64k)            (131072 B)
#define SM_W3   167936        // 4 k-chunks x (64n x 64k), PRE-SCALED BY dt (32768 B)
#define SMEM_BYTES 200704

#define SWZ(off) ((off) ^ (((off) >> 3) & 0x70))

// ======================= device helpers ==========================
__device__ __forceinline__ uint32_t smem_to_u32(const void* p) {
    uint32_t a;
    asm("{ .reg .u64 t; cvta.to.shared.u64 t, %1; cvt.u32.u64 %0, t; }" : "=r"(a) : "l"(p));
    return a;
}
__device__ __forceinline__ uint32_t pack_bf16x2(float lo, float hi) {
    uint32_t r;
    asm("cvt.rn.bf16x2.f32 %0, %1, %2;" : "=r"(r) : "f"(hi), "f"(lo));
    return r;
}
__device__ __forceinline__ float fast_tanh(float x) {
    float y;
    asm("tanh.approx.f32 %0, %1;" : "=f"(y) : "f"(x));
    return y;
}
__device__ __forceinline__ float silu(float a) {
    return a * (0.5f * fast_tanh(0.5f * a) + 0.5f);   // 1 MUFU op
}
__device__ __forceinline__ void ldsm4(uint32_t& r0, uint32_t& r1, uint32_t& r2, uint32_t& r3,
                                      uint32_t addr) {
    asm volatile("ldmatrix.sync.aligned.m8n8.x4.shared.b16 {%0,%1,%2,%3}, [%4];"
                 : "=r"(r0), "=r"(r1), "=r"(r2), "=r"(r3) : "r"(addr));
}
__device__ __forceinline__ void mma_bf16(float* c, const uint32_t* a, uint32_t b0, uint32_t b1) {
    asm volatile("mma.sync.aligned.m16n8k16.row.col.f32.bf16.bf16.f32 "
                 "{%0,%1,%2,%3}, {%4,%5,%6,%7}, {%8,%9}, {%0,%1,%2,%3};"
                 : "+f"(c[0]), "+f"(c[1]), "+f"(c[2]), "+f"(c[3])
                 : "r"(a[0]), "r"(a[1]), "r"(a[2]), "r"(a[3]), "r"(b0), "r"(b1));
}

// ======================= kernel ==================================
__global__ void __launch_bounds__(NTHREADS, 1) flow_kernel(
    const float* __restrict__ x0, const float* __restrict__ W1,
    const float* __restrict__ b1, const float* __restrict__ W2,
    const float* __restrict__ b2, const float* __restrict__ W3,
    const float* __restrict__ b3, float* __restrict__ out)
{
    extern __shared__ char smem[];
    const uint32_t sbase = smem_to_u32(smem);
    const int tid  = threadIdx.x;
    const int wid  = tid >> 5;
    const int lane = tid & 31;

    float* sb1  = (float*)(smem + SM_B1);
    float* stw1 = (float*)(smem + SM_TW1);
    float* sb2  = (float*)(smem + SM_B2);
    float* sdb3 = (float*)(smem + SM_DB3);

    const float dt = 1.0f / NSTEPS;

    // ---------------- prologue: biases ----------------
    for (int i = tid; i < HIDX; i += NTHREADS) {
        sb1[i]  = b1[i];
        stw1[i] = W1[DIMX * HIDX + i];   // t-row of W1
        sb2[i]  = b2[i];
    }
    if (tid < DIMX) sdb3[tid] = dt * b3[tid];

    // ---------------- prologue: weights -> bf16, W^T layout (n rows, k contig), SW128 ----
    for (int idx = tid; idx < DIMX * HIDX; idx += NTHREADS) {          // W1 (64k,256n)
        int k = idx >> 8, n = idx & 255;
        uint32_t off = (uint32_t)(n * 128 + k * 2);
        *(__nv_bfloat16*)(smem + SM_W1 + SWZ(off)) = __float2bfloat16(W1[idx]);
    }
    for (int idx = tid; idx < HIDX * HIDX; idx += NTHREADS) {          // W2 (256k,256n)
        int k = idx >> 8, n = idx & 255;
        int c = k >> 6, kk = k & 63;
        uint32_t off = (uint32_t)(n * 128 + kk * 2);
        *(__nv_bfloat16*)(smem + SM_W2 + c * 32768 + SWZ(off)) = __float2bfloat16(W2[idx]);
    }
    for (int idx = tid; idx < HIDX * DIMX; idx += NTHREADS) {          // W3 (256k,64n), x dt
        int k = idx >> 6, n = idx & 63;
        int c = k >> 6, kk = k & 63;
        uint32_t off = (uint32_t)(n * 128 + kk * 2);
        *(__nv_bfloat16*)(smem + SM_W3 + c * 8192 + SWZ(off)) = __float2bfloat16(dt * W3[idx]);
    }
    __syncthreads();

    // ---------------- per-lane ldmatrix addressing ----------------
    const int r = lane & 7, g = lane >> 3;
    const uint32_t ld_row = (uint32_t)((r + ((g >> 1) << 3)) * 128);
    const uint32_t g1 = (uint32_t)(g & 1);
    #define KOFF(kt) ((((uint32_t)(((kt) << 1) | g1) ^ (uint32_t)r) << 4))

    // ---------------- load x: m16 per warp, fp32 C-fragment layout ----------------
    const long rowA = (long)blockIdx.x * MTILE + wid * 16 + (lane >> 2);
    const long rowB = rowA + 8;
    const int  q2 = (lane & 3) * 2;

    float x[32];
    #pragma unroll
    for (int nt = 0; nt < 8; nt++) {
        float2 a = *(const float2*)(x0 + rowA * DIMX + nt * 8 + q2);
        float2 b = *(const float2*)(x0 + rowB * DIMX + nt * 8 + q2);
        x[nt * 4 + 0] = a.x; x[nt * 4 + 1] = a.y;
        x[nt * 4 + 2] = b.x; x[nt * 4 + 3] = b.y;
    }

    uint32_t hA[64];   // GEMM2 A fragments: [kt*4 + j], kt=0..15

    // ---- pipeline stage macros (m16) ----
    // GEMM1 mma for one 16-col pair into C[8]
    #define G1_MMA(pair, C) do { \
        const uint32_t _b = sbase + SM_W1 + (uint32_t)((pair) * 2048) + ld_row; \
        _Pragma("unroll") for (int _kt = 0; _kt < 4; _kt++) { \
            uint32_t _w0, _w1, _w2, _w3; \
            ldsm4(_w0, _w1, _w2, _w3, _b + KOFF(_kt)); \
            mma_bf16((C) + 0, xA + _kt * 4, _w0, _w1); \
            mma_bf16((C) + 4, xA + _kt * 4, _w2, _w3); } } while (0)

    // GEMM1 epilogue for one pair: hA[pair] = bf16(silu(C + b1 + t*tw1))
    #define G1_EPI(pair, C) do { \
        const int _c0 = (pair) * 16 + q2; \
        float2 _bA = *(const float2*)(sb1 + _c0); \
        float2 _tA = *(const float2*)(stw1 + _c0); \
        float2 _bB = *(const float2*)(sb1 + _c0 + 8); \
        float2 _tB = *(const float2*)(stw1 + _c0 + 8); \
        const float _ax = fmaf(tval, _tA.x, _bA.x), _ay = fmaf(tval, _tA.y, _bA.y); \
        const float _bx = fmaf(tval, _tB.x, _bB.x), _by = fmaf(tval, _tB.y, _bB.y); \
        uint32_t* _h = hA + (pair) * 4; \
        _h[0] = pack_bf16x2(silu((C)[0] + _ax), silu((C)[1] + _ay)); \
        _h[1] = pack_bf16x2(silu((C)[2] + _ax), silu((C)[3] + _ay)); \
        _h[2] = pack_bf16x2(silu((C)[4] + _bx), silu((C)[5] + _by)); \
        _h[3] = pack_bf16x2(silu((C)[6] + _bx), silu((C)[7] + _by)); } while (0)

    // GEMM2 mma for one 32-col chunk into C2[16]
    #define G2_MMA(ch, C2) do { \
        const uint32_t _b = sbase + SM_W2 + (uint32_t)((ch) * 4096) + ld_row; \
        _Pragma("unroll") for (int _kt = 0; _kt < 16; _kt++) { \
            const uint32_t _ko = (uint32_t)((_kt >> 2) * 32768) + KOFF(_kt & 3); \
            uint32_t _w0, _w1, _w2, _w3; \
            ldsm4(_w0, _w1, _w2, _w3, _b + _ko); \
            mma_bf16((C2) + 0, hA + _kt * 4, _w0, _w1); \
            mma_bf16((C2) + 4, hA + _kt * 4, _w2, _w3); \
            ldsm4(_w0, _w1, _w2, _w3, _b + 2048u + _ko); \
            mma_bf16((C2) + 8,  hA + _kt * 4, _w0, _w1); \
            mma_bf16((C2) + 12, hA + _kt * 4, _w2, _w3); } } while (0)

    // GEMM2 epilogue + GEMM3 k-slice: x += bf16(silu(C2 + b2)) @ (dt*W3)
    #define G23_EPI(ch, C2) do { \
        uint32_t _gA[8]; \
        _Pragma("unroll") for (int _p = 0; _p < 2; _p++) { \
            const int _c0 = (ch) * 32 + _p * 16 + q2; \
            float2 _bA = *(const float2*)(sb2 + _c0); \
            float2 _bB = *(const float2*)(sb2 + _c0 + 8); \
            const float* _c = (C2) + _p * 8; \
            _gA[_p * 4 + 0] = pack_bf16x2(silu(_c[0] + _bA.x), silu(_c[1] + _bA.y)); \
            _gA[_p * 4 + 1] = pack_bf16x2(silu(_c[2] + _bA.x), silu(_c[3] + _bA.y)); \
            _gA[_p * 4 + 2] = pack_bf16x2(silu(_c[4] + _bB.x), silu(_c[5] + _bB.y)); \
            _gA[_p * 4 + 3] = pack_bf16x2(silu(_c[6] + _bB.x), silu(_c[7] + _bB.y)); } \
        _Pragma("unroll") for (int _p = 0; _p < 2; _p++) { \
            const int _kt3 = (ch) * 2 + _p; \
            const uint32_t _b3 = sbase + SM_W3 + (uint32_t)((_kt3 >> 2) * 8192) + ld_row; \
            const uint32_t _ko = KOFF(_kt3 & 3); \
            _Pragma("unroll") for (int _nt = 0; _nt < 4; _nt++) { \
                uint32_t _w0, _w1, _w2, _w3; \
                ldsm4(_w0, _w1, _w2, _w3, _b3 + (uint32_t)(_nt * 2048) + _ko); \
                mma_bf16(x + (2 * _nt) * 4,     _gA + _p * 4, _w0, _w1); \
                mma_bf16(x + (2 * _nt + 1) * 4, _gA + _p * 4, _w2, _w3); } } } while (0)

    #define ZERO8(C)  { _Pragma("unroll") for (int _i = 0; _i < 8;  _i++) (C)[_i] = 0.0f; }
    #define ZERO16(C) { _Pragma("unroll") for (int _i = 0; _i < 16; _i++) (C)[_i] = 0.0f; }

    #pragma unroll 1
    for (int s = 0; s < NSTEPS; s++) {
        const float tval = ((float)s + 0.5f) * dt;

        // ---- x -> bf16 A fragments for GEMM1: xA[kt*4+j], kt=0..3 ----
        uint32_t xA[16];
        #pragma unroll
        for (int kt = 0; kt < 4; kt++) {
            const float* xs = x + 2 * kt * 4;   // n-tiles 2kt, 2kt+1
            uint32_t* a = xA + kt * 4;
            a[0] = pack_bf16x2(xs[0], xs[1]);
            a[1] = pack_bf16x2(xs[2], xs[3]);
            a[2] = pack_bf16x2(xs[4], xs[5]);
            a[3] = pack_bf16x2(xs[6], xs[7]);
        }

        // ======== GEMM1 (software-pipelined over 16 pairs) ========
        {
            float Ca[8], Cb[8];
            ZERO8(Ca); G1_MMA(0, Ca);
            #pragma unroll 1
            for (int pi = 0; pi < 16; pi += 2) {
                ZERO8(Cb); G1_MMA(pi + 1, Cb);      // overlaps epi of pi
                G1_EPI(pi, Ca);
                if (pi < 14) { ZERO8(Ca); G1_MMA(pi + 2, Ca); }  // overlaps epi of pi+1
                G1_EPI(pi + 1, Cb);
            }
        }

        // ======== GEMM2+3 (software-pipelined over 8 chunks of 32 cols) ========
        {
            float C2a[16], C2b[16];
            ZERO16(C2a); G2_MMA(0, C2a);
            #pragma unroll 1
            for (int ch = 0; ch < 8; ch += 2) {
                ZERO16(C2b); G2_MMA(ch + 1, C2b);   // overlaps epi of ch
                G23_EPI(ch, C2a);
                if (ch < 6) { ZERO16(C2a); G2_MMA(ch + 2, C2a); }
                G23_EPI(ch + 1, C2b);
            }
        }

        // ---- x += dt * b3 (linear contribution) ----
        #pragma unroll
        for (int nt = 0; nt < 8; nt++) {
            float2 p = *(const float2*)(sdb3 + nt * 8 + q2);
            float* xs = x + nt * 4;
            xs[0] += p.x; xs[1] += p.y; xs[2] += p.x; xs[3] += p.y;
        }
    }

    // ---------------- store result ----------------
    #pragma unroll
    for (int nt = 0; nt < 8; nt++) {
        const float* xs = x + nt * 4;
        *(float2*)(out + rowA * DIMX + nt * 8 + q2) = make_float2(xs[0], xs[1]);
        *(float2*)(out + rowB * DIMX + nt * 8 + q2) = make_float2(xs[2], xs[3]);
    }
}

// ======================= launch ==================================
extern "C" void kernel_launch(void* const* d_in, const int* in_sizes, int n_in,
                              void* d_out, int out_size) {
    const float* x0 = (const float*)d_in[0];
    const float* W1 = (const float*)d_in[1];
    const float* b1 = (const float*)d_in[2];
    const float* W2 = (const float*)d_in[3];
    const float* b2 = (const float*)d_in[4];
    const float* W3 = (const float*)d_in[5];
    const float* b3 = (const float*)d_in[6];
    float* out = (float*)d_out;

    const int nrows = in_sizes[0] / DIMX;
    const int grid  = nrows / MTILE;   // 1024

    cudaFuncSetAttribute(flow_kernel, cudaFuncAttributeMaxDynamicSharedMemorySize, SMEM_BYTES);
    flow_kernel<<<grid, NTHREADS, SMEM_BYTES>>>(x0, W1, b1, W2, b2, W3, b3, out);
}